// round 1
// baseline (speedup 1.0000x reference)
#include <cuda_runtime.h>
#include <cuda_bf16.h>
#include <math.h>

// Problem constants
#define BATCH 32
#define CIN   128
#define HH    64
#define WW    64
#define HW    (HH*WW)          // 4096
#define EMB   384
#define EB    128              // per-branch out channels
#define HID   24               // 384/16

// ---------------- scratch (device globals; no allocations allowed) ----------
__device__ float g_fused[(size_t)BATCH * EMB * HW];   // conv concat output [B,E,H,W]
__device__ float g_gout [(size_t)BATCH * EMB * HW];   // 1x1 fusion output  [B,E,H,W]
__device__ float g_avg  [BATCH * EMB];
__device__ float g_max  [BATCH * EMB];
__device__ float g_attn [BATCH * EMB];

// ---------------------------------------------------------------------------
// Kernel 1: direct conv, K in {3,5,7}.  Block = (h, b). 256 threads.
// Each block computes all 128 output channels for one output row (64 w).
// Thread tile: 4 oc x 8 w.
// ---------------------------------------------------------------------------
template<int K>
__global__ __launch_bounds__(256, 2)
void conv_kernel(const float* __restrict__ x, const float* __restrict__ wgt,
                 const float* __restrict__ bias, float* __restrict__ out,
                 int ch_off)
{
    constexpr int HALO = K / 2;
    constexpr int WIN  = WW + K - 1;
    constexpr int KK   = K * K;

    __shared__ float s_w[EB * KK];     // weights for all 128 oc, current c
    __shared__ float s_in[K][WIN];     // K input rows (with halo), current c

    const int h = blockIdx.x;
    const int b = blockIdx.y;
    const int t = threadIdx.x;

    const int wg  = t & 7;        // 8 groups of 8 w
    const int ocg = t >> 3;       // 32 groups of 4 oc
    const int w0  = wg * 8;

    float acc[4][8];
#pragma unroll
    for (int i = 0; i < 4; ++i)
#pragma unroll
        for (int j = 0; j < 8; ++j) acc[i][j] = 0.f;

    const float* xb = x + (size_t)b * CIN * HW;

    for (int c = 0; c < CIN; ++c) {
        __syncthreads();
        // stage weights for this input channel: w[oc][c][kh][kw]
        const float* wc = wgt + (size_t)c * KK;
        for (int i = t; i < EB * KK; i += 256) {
            int oc = i / KK;
            int j  = i - oc * KK;
            s_w[i] = wc[(size_t)oc * CIN * KK + j];
        }
        // stage input rows (zero-padded)
        const float* xc = xb + (size_t)c * HW;
        for (int i = t; i < K * WIN; i += 256) {
            int kh  = i / WIN;
            int col = i - kh * WIN;
            int r   = h - HALO + kh;
            int cc  = col - HALO;
            float v = 0.f;
            if (r >= 0 && r < HH && cc >= 0 && cc < WW) v = xc[r * WW + cc];
            s_in[kh][col] = v;
        }
        __syncthreads();

#pragma unroll
        for (int kh = 0; kh < K; ++kh) {
            float in[8 + K - 1];
#pragma unroll
            for (int j = 0; j < 8 + K - 1; ++j) in[j] = s_in[kh][w0 + j];
#pragma unroll
            for (int i = 0; i < 4; ++i) {
                const float* wrow = &s_w[(ocg * 4 + i) * KK + kh * K];
#pragma unroll
                for (int kw = 0; kw < K; ++kw) {
                    float wv = wrow[kw];
#pragma unroll
                    for (int j = 0; j < 8; ++j)
                        acc[i][j] = fmaf(in[kw + j], wv, acc[i][j]);
                }
            }
        }
    }

    // write: out[b][ch_off+oc][h][w0..w0+8)
#pragma unroll
    for (int i = 0; i < 4; ++i) {
        int oc = ocg * 4 + i;
        float bv = bias[oc];
        float4 v0 = make_float4(acc[i][0] + bv, acc[i][1] + bv, acc[i][2] + bv, acc[i][3] + bv);
        float4 v1 = make_float4(acc[i][4] + bv, acc[i][5] + bv, acc[i][6] + bv, acc[i][7] + bv);
        float* dst = out + (((size_t)b * EMB + ch_off + oc) * HH + h) * WW + w0;
        *reinterpret_cast<float4*>(dst)     = v0;
        *reinterpret_cast<float4*>(dst + 4) = v1;
    }
}

// ---------------------------------------------------------------------------
// Kernel 2: global avg + max pool per (b, e). Block = (e, b), 256 threads.
// ---------------------------------------------------------------------------
__global__ __launch_bounds__(256)
void pool_kernel(const float* __restrict__ fused,
                 float* __restrict__ avg_out, float* __restrict__ max_out)
{
    const int e = blockIdx.x;
    const int b = blockIdx.y;
    const int t = threadIdx.x;

    const float4* p = reinterpret_cast<const float4*>(fused + ((size_t)b * EMB + e) * HW);

    float s = 0.f, m = -INFINITY;
#pragma unroll
    for (int i = 0; i < 4; ++i) {
        float4 v = p[t + i * 256];
        s += v.x + v.y + v.z + v.w;
        m = fmaxf(m, fmaxf(fmaxf(v.x, v.y), fmaxf(v.z, v.w)));
    }

    __shared__ float ss[256], sm[256];
    ss[t] = s; sm[t] = m;
    __syncthreads();
    for (int o = 128; o > 0; o >>= 1) {
        if (t < o) { ss[t] += ss[t + o]; sm[t] = fmaxf(sm[t], sm[t + o]); }
        __syncthreads();
    }
    if (t == 0) {
        avg_out[b * EMB + e] = ss[0] * (1.f / (float)HW);
        max_out[b * EMB + e] = sm[0];
    }
}

// ---------------------------------------------------------------------------
// Kernel 3: CBAM MLP + sigmoid. One block per batch, 384 threads.
// attn = sigmoid( relu(avg@W1^T)@W2^T + relu(max@W1^T)@W2^T )
// ---------------------------------------------------------------------------
__global__ __launch_bounds__(EMB)
void attn_kernel(const float* __restrict__ avg_in, const float* __restrict__ max_in,
                 const float* __restrict__ w1,      // [HID, EMB]
                 const float* __restrict__ w2,      // [EMB, HID]
                 float* __restrict__ attn)
{
    const int b = blockIdx.x;
    const int t = threadIdx.x;

    __shared__ float s_avg[EMB], s_max[EMB];
    __shared__ float s_h[HID];     // relu(ha)+relu(hm)
    __shared__ float s_ha[HID], s_hm[HID];

    s_avg[t] = avg_in[b * EMB + t];
    s_max[t] = max_in[b * EMB + t];
    __syncthreads();

    if (t < HID) {
        float a = 0.f;
        const float* w1r = w1 + t * EMB;
        for (int e = 0; e < EMB; ++e) a = fmaf(s_avg[e], w1r[e], a);
        s_ha[t] = fmaxf(a, 0.f);
    } else if (t >= 32 && t < 32 + HID) {
        int j = t - 32;
        float a = 0.f;
        const float* w1r = w1 + j * EMB;
        for (int e = 0; e < EMB; ++e) a = fmaf(s_max[e], w1r[e], a);
        s_hm[j] = fmaxf(a, 0.f);
    }
    __syncthreads();
    if (t < HID) s_h[t] = s_ha[t] + s_hm[t];
    __syncthreads();

    float v = 0.f;
    const float* w2r = w2 + t * HID;
#pragma unroll
    for (int j = 0; j < HID; ++j) v = fmaf(s_h[j], w2r[j], v);
    attn[b * EMB + t] = 1.f / (1.f + expf(-v));
}

// ---------------------------------------------------------------------------
// Kernel 4: 1x1 fusion conv as GEMM with attn scaling fused into A load.
// g_gout[b,o,hw] = sum_c fused[b,c,hw]*attn[b,c]*Wf[o,c] + fb[o]
// Block tile: 384 o x 32 hw.  Thread tile: 6 o x 8 hw.  c-chunks of 16.
// Grid: (HW/32, B), 256 threads.
// ---------------------------------------------------------------------------
#define CCHUNK 16
__global__ __launch_bounds__(256, 2)
void fusion_kernel(const float* __restrict__ fused, const float* __restrict__ attn,
                   const float* __restrict__ wf,   // [EMB, EMB] row-major [o][c]
                   const float* __restrict__ fb,
                   float* __restrict__ out)
{
    __shared__ float s_wf[EMB * (CCHUNK + 1)];   // [o][c] padded
    __shared__ float s_in[CCHUNK * 32];          // [c][hw]

    const int hw0 = blockIdx.x * 32;
    const int b   = blockIdx.y;
    const int t   = threadIdx.x;

    const int hwg = t & 3;        // 4 groups of 8 hw
    const int ocg = t >> 2;       // 64 groups of 6 oc
    const int hwb = hwg * 8;

    float acc[6][8];
#pragma unroll
    for (int i = 0; i < 6; ++i)
#pragma unroll
        for (int j = 0; j < 8; ++j) acc[i][j] = 0.f;

    const float* fb_base  = fused + (size_t)b * EMB * HW + hw0;
    const float* attn_b   = attn + b * EMB;

    for (int cb = 0; cb < EMB; cb += CCHUNK) {
        __syncthreads();
        // weights tile: [o][c] -> padded shared
        for (int i = t; i < EMB * CCHUNK; i += 256) {
            int o = i >> 4;           // /16
            int c = i & 15;
            s_wf[o * (CCHUNK + 1) + c] = wf[(size_t)o * EMB + cb + c];
        }
        // input tile, scaled by attn
        for (int i = t; i < CCHUNK * 32; i += 256) {
            int c  = i >> 5;
            int hw = i & 31;
            s_in[c * 32 + hw] = fb_base[(size_t)(cb + c) * HW + hw] * attn_b[cb + c];
        }
        __syncthreads();

#pragma unroll
        for (int c = 0; c < CCHUNK; ++c) {
            float inr[8];
#pragma unroll
            for (int j = 0; j < 8; ++j) inr[j] = s_in[c * 32 + hwb + j];
#pragma unroll
            for (int i = 0; i < 6; ++i) {
                float wv = s_wf[(ocg * 6 + i) * (CCHUNK + 1) + c];
#pragma unroll
                for (int j = 0; j < 8; ++j)
                    acc[i][j] = fmaf(inr[j], wv, acc[i][j]);
            }
        }
    }

#pragma unroll
    for (int i = 0; i < 6; ++i) {
        int o = ocg * 6 + i;
        float bv = fb[o];
        float* dst = out + ((size_t)b * EMB + o) * HW + hw0 + hwb;
        float4 v0 = make_float4(acc[i][0] + bv, acc[i][1] + bv, acc[i][2] + bv, acc[i][3] + bv);
        float4 v1 = make_float4(acc[i][4] + bv, acc[i][5] + bv, acc[i][6] + bv, acc[i][7] + bv);
        *reinterpret_cast<float4*>(dst)     = v0;
        *reinterpret_cast<float4*>(dst + 4) = v1;
    }
}

// ---------------------------------------------------------------------------
// Kernel 5: transpose [B,E,HW] -> [B,HW,E] + LayerNorm over E per token.
// Block handles 16 tokens of one batch. 256 threads (8 warps x 2 tokens).
// ---------------------------------------------------------------------------
__global__ __launch_bounds__(256)
void ln_kernel(const float* __restrict__ g, const float* __restrict__ gamma,
               const float* __restrict__ beta, float* __restrict__ out)
{
    __shared__ float s[EMB * 17];   // [e][tok] padded (16 tokens + 1)

    const int hw0 = blockIdx.x * 16;
    const int b   = blockIdx.y;
    const int t   = threadIdx.x;

    // load tile: g[b][e][hw0 + tok], coalesced over tok rows of 16
    const float* gb = g + (size_t)b * EMB * HW + hw0;
    for (int i = t; i < EMB * 16; i += 256) {
        int e   = i >> 4;
        int tok = i & 15;
        s[e * 17 + tok] = gb[(size_t)e * HW + tok];
    }
    __syncthreads();

    const int warp = t >> 5;
    const int lane = t & 31;

#pragma unroll
    for (int tt = 0; tt < 2; ++tt) {
        int tok = warp * 2 + tt;
        // each lane handles e = lane + 32k, k<12
        float vals[12];
        float sum = 0.f, sq = 0.f;
#pragma unroll
        for (int k = 0; k < 12; ++k) {
            float v = s[(lane + 32 * k) * 17 + tok];
            vals[k] = v;
            sum += v;
            sq  = fmaf(v, v, sq);
        }
#pragma unroll
        for (int o = 16; o > 0; o >>= 1) {
            sum += __shfl_xor_sync(0xFFFFFFFFu, sum, o);
            sq  += __shfl_xor_sync(0xFFFFFFFFu, sq,  o);
        }
        float mu  = sum * (1.f / (float)EMB);
        float var = sq * (1.f / (float)EMB) - mu * mu;
        float rstd = rsqrtf(var + 1e-5f);

        float* dst = out + ((size_t)b * HW + hw0 + tok) * EMB;
#pragma unroll
        for (int k = 0; k < 12; ++k) {
            int e = lane + 32 * k;
            dst[e] = (vals[k] - mu) * rstd * gamma[e] + beta[e];
        }
    }
}

// ---------------------------------------------------------------------------
// Launcher.  Inputs (metadata order):
//  0:x  1:w3 2:b3 3:w5 4:b5 5:w7 6:b7 7:ca_w1 8:ca_w2 9:fusion_w 10:fusion_b
//  11:ln_g 12:ln_b
// ---------------------------------------------------------------------------
extern "C" void kernel_launch(void* const* d_in, const int* in_sizes, int n_in,
                              void* d_out, int out_size)
{
    const float* x   = (const float*)d_in[0];
    const float* w3  = (const float*)d_in[1];
    const float* b3  = (const float*)d_in[2];
    const float* w5  = (const float*)d_in[3];
    const float* b5  = (const float*)d_in[4];
    const float* w7  = (const float*)d_in[5];
    const float* b7  = (const float*)d_in[6];
    const float* cw1 = (const float*)d_in[7];
    const float* cw2 = (const float*)d_in[8];
    const float* fw  = (const float*)d_in[9];
    const float* fbi = (const float*)d_in[10];
    const float* lng = (const float*)d_in[11];
    const float* lnb = (const float*)d_in[12];
    float* out = (float*)d_out;

    float* fused; cudaGetSymbolAddress((void**)&fused, g_fused);
    float* gout;  cudaGetSymbolAddress((void**)&gout,  g_gout);
    float* gavg;  cudaGetSymbolAddress((void**)&gavg,  g_avg);
    float* gmax;  cudaGetSymbolAddress((void**)&gmax,  g_max);
    float* gattn; cudaGetSymbolAddress((void**)&gattn, g_attn);

    dim3 cgrid(HH, BATCH);
    conv_kernel<3><<<cgrid, 256>>>(x, w3, b3, fused, 0);
    conv_kernel<5><<<cgrid, 256>>>(x, w5, b5, fused, EB);
    conv_kernel<7><<<cgrid, 256>>>(x, w7, b7, fused, 2 * EB);

    pool_kernel<<<dim3(EMB, BATCH), 256>>>(fused, gavg, gmax);
    attn_kernel<<<BATCH, EMB>>>(gavg, gmax, cw1, cw2, gattn);

    fusion_kernel<<<dim3(HW / 32, BATCH), 256>>>(fused, gattn, fw, fbi, gout);

    ln_kernel<<<dim3(HW / 16, BATCH), 256>>>(gout, lng, lnb, out);
}